// round 11
// baseline (speedup 1.0000x reference)
#include <cuda_runtime.h>
#include <math.h>
#include <stdint.h>

#define NB     16
#define NA3    3
#define NGRID  76
#define NCELL  (NGRID*NGRID)        // 5776
#define CELLS  (NB*NCELL)           // 92416
#define KDIM   256
#define NBOX   50
#define NCLS   80
#define NCH    85                   // 5 + 80

#define MAIN_THREADS      128
#define BLK_PER_B         46                          // ceil(5776/128); last block has 16 cells
#define MAIN_BLOCKS       (NB*BLK_PER_B)              // 736
#define CLS_BLOCKS        (NB*NBOX)                   // 800
#define FAT_BLOCKS        (MAIN_BLOCKS + CLS_BLOCKS)  // 1536

#define C717  0.41176470588235294f   // 7/17, same literal everywhere

// ---- device scratch (no allocation allowed) ----
__device__ float4 g_box[NB*NBOX];           // gt box corners x1,y1,x2,y2 (grid units)
__device__ float  g_area[NB*NBOX];          // gt area (unscaled)
__device__ int    g_win[NB*NBOX];           // anchor if this GT is the winning writer, else -1
__device__ int    g_hw[NB*NBOX];            // cell index for winner
__device__ float  g_obj[MAIN_BLOCKS];       // per-main-block noobj loss partial
__device__ float4 g_corr[NB*NBOX];          // per-GT correction (xy, wh, obj, cls)
__device__ unsigned long long g_W2[(KDIM/2)*16];  // paired weights {w_2kp, w_2kp+1}
__device__ int    g_count;                  // completed-block counter

// ALL_ANCHORS = ANCHORS_PX / 8
__constant__ float c_aw[9] = {1.25f, 2.0f, 4.125f, 3.75f, 7.75f, 7.375f, 14.5f, 19.5f, 46.625f};
__constant__ float c_ah[9] = {1.625f, 3.75f, 2.875f, 7.625f, 5.625f, 14.875f, 11.25f, 24.75f, 40.75f};

__device__ __forceinline__ float safelog(float p) {
    return fmaxf(logf(fmaxf(p, 1e-12f)), -100.0f);
}
__device__ __forceinline__ float bce(float p, float t) {
    return -(t * safelog(p) + (1.0f - t) * safelog(1.0f - p));
}
__device__ __forceinline__ float sigm(float x) {
    return 1.0f / (1.0f + expf(-x));
}
__device__ __forceinline__ unsigned long long pack2(float lo, float hi) {
    unsigned long long r;
    asm("mov.b64 %0, {%1, %2};" : "=l"(r) : "f"(lo), "f"(hi));
    return r;
}
__device__ __forceinline__ float2 unpack2(unsigned long long p) {
    float2 q;
    asm("mov.b64 {%0, %1}, %2;" : "=f"(q.x), "=f"(q.y) : "l"(p));
    return q;
}
__device__ __forceinline__ void fma2(unsigned long long& d, unsigned long long a, unsigned long long b) {
    asm("fma.rn.f32x2 %0, %1, %2, %0;" : "+l"(d) : "l"(a), "l"(b));
}
__device__ __forceinline__ void cp16(uint32_t dst, const void* src) {
    asm volatile("cp.async.cg.shared.global [%0], [%1], 16;" :: "r"(dst), "l"(src));
}
__device__ __forceinline__ void cp_commit() {
    asm volatile("cp.async.commit_group;" ::: "memory");
}
__device__ __forceinline__ void cp_wait2() {
    asm volatile("cp.async.wait_group 2;" ::: "memory");
}

// ---- shared memory union for the fat kernel ----
struct __align__(16) SmemMain {
    unsigned long long W2[(KDIM/2)*16];      // 16384 B (offset 0)
    float st[3][8][MAIN_THREADS];            // 12288 B (3-stage pipeline)
    float4 Box[NBOX];                        // single batch per block
    float  Area[NBOX];                       // pre-scaled by 7/17
    float  B[15];
    float  red[MAIN_THREADS];
};
struct SmemCls {
    float xcol[KDIM];
    float spart[NCH*33];
    float zfull[NCH];
    float lred[NCLS];
    float siou[48];
};
struct SmemFin {
    float4 r4[MAIN_THREADS];
};
union SmemU { SmemMain m; SmemCls c; SmemFin f; };

// ---- kernel 0: anchor matching (block 0) + weight packing (blocks 1..3) ----
__global__ void __launch_bounds__(800) k_prep(const float* __restrict__ labels,
                                              const float* __restrict__ Wm) {
    int t = threadIdx.x;
    if (blockIdx.x > 0) {
        int i = (blockIdx.x - 1)*800 + t;                 // 0..2399
        if (i < (KDIM/2)*16) {
            int kp = i >> 4, o = i & 15;
            unsigned long long v = 0ull;
            if (o < 15) {
                int row = (o/5)*NCH + (o%5);
                v = pack2(Wm[row*KDIM + 2*kp], Wm[row*KDIM + 2*kp + 1]);
            }
            g_W2[i] = v;
        }
        return;
    }
    if (t == 0) g_count = 0;
    __shared__ int sk[NB*NBOX];
    int b = t / NBOX, n = t % NBOX;
    const float* l = labels + t*5;
    float l0=l[0], l1=l[1], l2=l[2], l3=l[3], l4=l[4];
    bool valid = (l0 + l1 + l2 + l3 + l4) > 0.0f;
    float gx = l1*NGRID, gy = l2*NGRID, gw = l3*NGRID, gh = l4*NGRID;
    if (!valid) { gx = 0.f; gy = 0.f; gw = 0.f; gh = 0.f; }
    g_box[t] = make_float4(gx - 0.5f*gw, gy - 0.5f*gh, gx + 0.5f*gw, gy + 0.5f*gh);
    g_area[t] = gw * gh;
    int best = 0; float bv = -1.0f;
    #pragma unroll
    for (int i = 0; i < 9; i++) {
        float inter = fminf(gw, c_aw[i]) * fminf(gh, c_ah[i]);
        float uni   = gw*gh + c_aw[i]*c_ah[i] - inter;
        float r = inter / uni;
        if (r > bv) { bv = r; best = i; }
    }
    int a = (valid && best <= 2) ? best : -1;
    int gi = (int)floorf(gx), gj = (int)floorf(gy);
    bool inb = (a >= 0) && gi >= 0 && gi < NGRID && gj >= 0 && gj < NGRID;
    int key = inb ? ((a*NGRID + gj)*NGRID + gi) : (-1 - t);   // unique negatives
    sk[t] = key;
    __syncthreads();
    bool winner = inb;
    const int* skb = sk + b*NBOX;
    for (int m = n + 1; m < NBOX; m++)
        if (skb[m] == key) winner = false;
    g_win[t] = winner ? a : -1;
    g_hw[t]  = winner ? (gj*NGRID + gi) : 0;
}

// ---- winner path: full 85-channel conv at the assigned cell + correction losses ----
__device__ void cls_path(SmemCls* s, int gid,
        const float* __restrict__ xin, const float* __restrict__ labels,
        const float* __restrict__ Wm, const float* __restrict__ bias) {
    int tid = threadIdx.x;
    int a = g_win[gid];
    if (a < 0) {
        if (tid == 0) g_corr[gid] = make_float4(0.f, 0.f, 0.f, 0.f);
        return;
    }
    int b  = gid / NBOX;
    int hw = g_hw[gid];

    const float* src = xin + (size_t)b * KDIM * NCELL + hw;
    s->xcol[tid]       = src[(size_t)tid * NCELL];
    s->xcol[tid + 128] = src[(size_t)(tid + 128) * NCELL];
    __syncthreads();

    int warp = tid >> 5, lane = tid & 31;
    float4 xv0 = *reinterpret_cast<const float4*>(s->xcol + lane*8);
    float4 xv1 = *reinterpret_cast<const float4*>(s->xcol + lane*8 + 4);
    #pragma unroll 2
    for (int cc = 0; cc < 22; cc++) {
        int j = warp*22 + cc;                 // channel within anchor
        if (j < NCH) {
            const float4* wp = reinterpret_cast<const float4*>(
                Wm + (size_t)(a*NCH + j)*KDIM + lane*8);
            float4 wa = wp[0], wb = wp[1];
            float z = wa.x*xv0.x + wa.y*xv0.y + wa.z*xv0.z + wa.w*xv0.w
                    + wb.x*xv1.x + wb.y*xv1.y + wb.z*xv1.z + wb.w*xv1.w;
            s->spart[j*33 + lane] = z;
        }
    }
    __syncthreads();
    if (tid < NCH) {
        float sm = 0.0f;
        #pragma unroll 8
        for (int l = 0; l < 32; l++) sm += s->spart[tid*33 + l];
        s->zfull[tid] = sm + bias[a*NCH + tid];
    }
    __syncthreads();

    // decode (redundant across threads, cheap)
    float x0 = s->zfull[0], x1 = s->zfull[1], x2 = s->zfull[2];
    float x3 = s->zfull[3], x4 = s->zfull[4];
    float fx = (float)(hw % NGRID), fy = (float)(hw / NGRID);
    float sx = sigm(x0), sy = sigm(x1);
    float pw = expf(x2) * c_aw[a];
    float ph = expf(x3) * c_ah[a];
    float px = sx + fx, py = sy + fy;
    float pl = px - 0.5f*pw, pr = px + 0.5f*pw;
    float pt = py - 0.5f*ph, pb = py + 0.5f*ph;
    float cpa = C717 * (pw * ph);

    if (tid < NCLS) {
        float p = sigm(s->zfull[5 + tid]);
        int gtc = (int)labels[gid*5];
        s->lred[tid] = (tid == gtc) ? -safelog(p) : -safelog(1.0f - p);
    } else {
        // threads 80..127: IOU partials over boxes j and j+48
        int j0 = tid - 80;
        float bad = -1e30f;
        #pragma unroll
        for (int rep = 0; rep < 2; rep++) {
            int j = j0 + rep*48;
            if (j < NBOX) {
                float4 g = g_box[b*NBOX + j];
                float cga = C717 * g_area[b*NBOX + j];
                float tlx = fmaxf(pl, g.x);
                float tly = fmaxf(pt, g.y);
                float brx = fminf(pr, g.z);
                float bry = fminf(pb, g.w);
                float iw = fmaxf(brx - tlx, 0.0f);
                float ih = fmaxf(bry - tly, 0.0f);
                bad = fmaxf(bad, fmaf(iw, ih, -cga));
            }
        }
        s->siou[j0] = bad;
    }
    __syncthreads();

    if (tid == 0) {
        float bad = -1e30f;
        #pragma unroll 8
        for (int i = 0; i < 48; i++) bad = fmaxf(bad, s->siou[i]);
        bool noobj = (bad <= cpa);              // bestiou <= 0.7
        float conf = sigm(x4);
        float cobj = -safelog(conf);
        if (noobj) cobj -= -safelog(1.0f - conf);

        const float* l = labels + gid*5;
        float gx = l[1]*NGRID, gy = l[2]*NGRID;
        float gw = l[3]*NGRID, gh = l[4]*NGRID;
        float tx = gx - floorf(gx), ty = gy - floorf(gy);
        float sc = 2.0f - gw*gh * (1.0f/(float)(NGRID*NGRID));
        float cxy = sc * (bce(sx, tx) + bce(sy, ty));
        float tw = logf(gw / c_aw[a] + 1e-16f);
        float th = logf(gh / c_ah[a] + 1e-16f);
        float rs = sqrtf(sc);
        float dw = x2*rs - tw*rs, dh = x3*rs - th*rs;
        float cwh = 0.5f * (dw*dw + dh*dh);

        float ccls = 0.0f;
        #pragma unroll 8
        for (int i = 0; i < NCLS; i++) ccls += s->lred[i];
        g_corr[gid] = make_float4(cxy, cwh, cobj, ccls);
    }
}

// ---- main path: 3-stage cp.async 15-ch GEMM (k-paired f32x2) + noobj loss ----
__device__ void main_path(SmemMain* s, int mbid,
        const float* __restrict__ xin, const float* __restrict__ bias) {
    int tid = threadIdx.x;
    int b   = mbid / BLK_PER_B;
    int blk = mbid - b*BLK_PER_B;
    int hw0 = blk * 128;
    int act = NCELL - hw0; if (act > 128) act = 128;   // 128, or 16 for tail block

    // coalesced smem fill from packed global weights
    {
        const ulonglong2* gw = reinterpret_cast<const ulonglong2*>(g_W2);
        ulonglong2* sw = reinterpret_cast<ulonglong2*>(s->W2);
        #pragma unroll
        for (int i = 0; i < 8; i++) sw[tid + i*MAIN_THREADS] = gw[tid + i*MAIN_THREADS];
    }
    if (tid < 15) s->B[tid] = bias[(tid/5)*NCH + (tid%5)];
    for (int i = tid; i < NBOX; i += MAIN_THREADS) {
        s->Box[i]  = g_box[b*NBOX + i];
        s->Area[i] = C717 * g_area[b*NBOX + i];        // pre-scaled
    }

    // cp.async chunk mapping: each thread owns chunks (r0,col) and (r0+4,col)
    int r0  = tid >> 5;                    // 0..3
    int col = tid & 31;                    // 16B chunk within a 512B k-row
    bool cvalid = (col * 16) < (act * 4);
    const char* gA = (const char*)xin
        + ((size_t)(b*KDIM + r0) * NCELL + hw0) * 4 + (size_t)col * 16;
    const char* gB = gA + (size_t)4 * NCELL * 4;
    const size_t stride8 = (size_t)8 * NCELL * 4;      // advance 8 k-rows
    uint32_t dA = (uint32_t)__cvta_generic_to_shared(&s->st[0][0][0]) + r0*512 + col*16;
    uint32_t dB = dA + 4*512;

    // prologue: stages 0..2 in flight (groups g0,g1,g2)
    #pragma unroll
    for (int st0 = 0; st0 < 3; st0++) {
        if (cvalid) {
            cp16(dA + st0*4096, gA);
            cp16(dB + st0*4096, gB);
        }
        cp_commit();
        gA += stride8; gB += stride8;
    }

    __syncthreads();   // W2 / Box / B visible

    unsigned long long acc[15];
    #pragma unroll
    for (int o = 0; o < 15; o++) acc[o] = pack2(s->B[o], 0.0f);   // bias in lo half

    #pragma unroll 3
    for (int kb = 0; kb < 32; kb++) {
        cp_wait2();           // group g_kb complete (exactly 2 newer groups pending)
        __syncthreads();      // stage kb visible to all threads
        int bufi = kb % 3;
        #pragma unroll
        for (int i = 0; i < 4; i++) {
            float lo = s->st[bufi][2*i][tid];
            float hi = s->st[bufi][2*i + 1][tid];
            unsigned long long x2 = pack2(lo, hi);
            int kp = kb*4 + i;
            const ulonglong2* wp = reinterpret_cast<const ulonglong2*>(s->W2 + kp*16);
            #pragma unroll
            for (int j = 0; j < 7; j++) {
                ulonglong2 w2 = wp[j];
                fma2(acc[2*j],   w2.x, x2);
                fma2(acc[2*j+1], w2.y, x2);
            }
            fma2(acc[14], s->W2[kp*16 + 14], x2);
        }
        __syncthreads();      // all threads done reading buf kb%3 before reuse
        if (kb + 3 < 32) {
            if (cvalid) {
                cp16(dA + bufi*4096, gA);   // (kb+3)%3 == kb%3
                cp16(dB + bufi*4096, gB);
            }
            gA += stride8; gB += stride8;
        }
        cp_commit();          // UNCONDITIONAL: keeps wait_group arithmetic valid
    }

    float lobj = 0.f;
    if (tid < act) {
        int hw = hw0 + tid;
        float fx = (float)(hw % NGRID);
        float fy = (float)(hw / NGRID);
        float xs[15];
        #pragma unroll
        for (int o = 0; o < 15; o++) {
            float2 u = unpack2(acc[o]);
            xs[o] = u.x + u.y;               // even-k sum (+bias) + odd-k sum
        }
        #pragma unroll
        for (int a = 0; a < 3; a++) {        // anchors outer: fewer live regs
            float sx = sigm(xs[a*5+0]), sy = sigm(xs[a*5+1]);
            float pw = expf(xs[a*5+2]) * c_aw[a];
            float ph = expf(xs[a*5+3]) * c_ah[a];
            float px = sx + fx, py = sy + fy;
            float pl = px - 0.5f*pw, pr = px + 0.5f*pw;
            float pt = py - 0.5f*ph, pb = py + 0.5f*ph;
            float cpa = C717 * (pw * ph);
            float bad = -1e30f;
            #pragma unroll 2
            for (int j = 0; j < NBOX; j++) {
                float4 g = s->Box[j];
                float cga = s->Area[j];
                float tlx = fmaxf(pl, g.x);
                float tly = fmaxf(pt, g.y);
                float brx = fminf(pr, g.z);
                float bry = fminf(pb, g.w);
                float iw = fmaxf(brx - tlx, 0.0f);
                float ih = fmaxf(bry - tly, 0.0f);
                bad = fmaxf(bad, fmaf(iw, ih, -cga));
            }
            if (bad <= cpa) {                     // bestiou <= 0.7
                float conf = sigm(xs[a*5+4]);
                lobj += -safelog(1.0f - conf);
            }
        }
    }

    // single deterministic block reduction (obj only)
    float* sred = s->red;
    sred[tid] = lobj; __syncthreads();
    for (int st = MAIN_THREADS/2; st > 0; st >>= 1) {
        if (tid < st) sred[tid] += sred[tid+st];
        __syncthreads();
    }
    if (tid == 0) g_obj[mbid] = sred[0];
}

// ---- final reduction, run by the last block to finish ----
__device__ void final_path(SmemFin* s, float* __restrict__ out) {
    int tid = threadIdx.x;
    float oxy = 0.f, owh = 0.f, oobj = 0.f, ocls = 0.f;
    for (int i = tid; i < MAIN_BLOCKS; i += MAIN_THREADS) oobj += g_obj[i];
    for (int i = tid; i < NB*NBOX; i += MAIN_THREADS) {
        float4 c = g_corr[i];
        oxy += c.x; owh += c.y; oobj += c.z; ocls += c.w;
    }
    s->r4[tid] = make_float4(oxy, owh, oobj, ocls);
    __syncthreads();
    for (int st = MAIN_THREADS/2; st > 0; st >>= 1) {
        if (tid < st) {
            float4 a = s->r4[tid], b = s->r4[tid+st];
            s->r4[tid] = make_float4(a.x+b.x, a.y+b.y, a.z+b.z, a.w+b.w);
        }
        __syncthreads();
    }
    if (tid == 0) {
        float4 r = s->r4[0];
        out[0] = r.x + r.y + r.z + r.w;
        out[1] = r.x; out[2] = r.y; out[3] = r.z; out[4] = r.w;
    }
}

// ---- the fat kernel: main blocks [0,736), winner blocks [736,1536), fused finale ----
__global__ void __launch_bounds__(MAIN_THREADS, 7)
k_fat(const float* __restrict__ xin, const float* __restrict__ labels,
      const float* __restrict__ Wm, const float* __restrict__ bias,
      float* __restrict__ out) {
    __shared__ SmemU su;
    __shared__ bool is_last;
    int bid = blockIdx.x;
    if (bid < MAIN_BLOCKS) {
        main_path(&su.m, bid, xin, bias);
    } else {
        cls_path(&su.c, bid - MAIN_BLOCKS, xin, labels, Wm, bias);
    }
    // completion counter; last block reduces everything
    __threadfence();
    __syncthreads();
    if (threadIdx.x == 0) {
        int v = atomicAdd(&g_count, 1);
        is_last = (v == FAT_BLOCKS - 1);
    }
    __syncthreads();
    if (is_last) {
        __threadfence();
        final_path(&su.f, out);
    }
}

extern "C" void kernel_launch(void* const* d_in, const int* in_sizes, int n_in,
                              void* d_out, int out_size) {
    const float* xin    = (const float*)d_in[0];
    const float* labels = (const float*)d_in[1];
    const float* W      = (const float*)d_in[2];
    const float* b      = (const float*)d_in[3];
    float* out = (float*)d_out;

    k_prep<<<4, 800>>>(labels, W);
    k_fat <<<FAT_BLOCKS, MAIN_THREADS>>>(xin, labels, W, b, out);
}

// round 12
// speedup vs baseline: 1.0054x; 1.0054x over previous
#include <cuda_runtime.h>
#include <math.h>
#include <stdint.h>

#define NB     16
#define NA3    3
#define NGRID  76
#define NCELL  (NGRID*NGRID)        // 5776
#define CELLS  (NB*NCELL)           // 92416
#define KDIM   256
#define NBOX   50
#define NCLS   80
#define NCH    85                   // 5 + 80

#define MAIN_THREADS      128
#define BLK_PER_B         46                          // ceil(5776/128); last block has 16 cells
#define MAIN_BLOCKS       (NB*BLK_PER_B)              // 736
#define CLS_BLOCKS        (NB*NBOX)                   // 800
#define FAT_BLOCKS        (MAIN_BLOCKS + CLS_BLOCKS)  // 1536

#define C717  0.41176470588235294f   // 7/17, same literal everywhere

// ---- device scratch (no allocation allowed) ----
__device__ float  g_obj[MAIN_BLOCKS];       // per-main-block noobj loss partial
__device__ float4 g_corr[NB*NBOX];          // per-GT correction (xy, wh, obj, cls)
__device__ int    g_count = 0;              // completed-block counter (reset by finale)

// ALL_ANCHORS = ANCHORS_PX / 8
__constant__ float c_aw[9] = {1.25f, 2.0f, 4.125f, 3.75f, 7.75f, 7.375f, 14.5f, 19.5f, 46.625f};
__constant__ float c_ah[9] = {1.625f, 3.75f, 2.875f, 7.625f, 5.625f, 14.875f, 11.25f, 24.75f, 40.75f};

__device__ __forceinline__ float safelog(float p) {
    return fmaxf(logf(fmaxf(p, 1e-12f)), -100.0f);
}
__device__ __forceinline__ float bce(float p, float t) {
    return -(t * safelog(p) + (1.0f - t) * safelog(1.0f - p));
}
__device__ __forceinline__ float sigm(float x) {
    return 1.0f / (1.0f + expf(-x));
}
__device__ __forceinline__ unsigned long long pack2(float lo, float hi) {
    unsigned long long r;
    asm("mov.b64 %0, {%1, %2};" : "=l"(r) : "f"(lo), "f"(hi));
    return r;
}
__device__ __forceinline__ float2 unpack2(unsigned long long p) {
    float2 q;
    asm("mov.b64 {%0, %1}, %2;" : "=f"(q.x), "=f"(q.y) : "l"(p));
    return q;
}
__device__ __forceinline__ void fma2(unsigned long long& d, unsigned long long a, unsigned long long b) {
    asm("fma.rn.f32x2 %0, %1, %2, %0;" : "+l"(d) : "l"(a), "l"(b));
}
__device__ __forceinline__ void cp16(uint32_t dst, const void* src) {
    asm volatile("cp.async.cg.shared.global [%0], [%1], 16;" :: "r"(dst), "l"(src));
}
__device__ __forceinline__ void cp_commit() {
    asm volatile("cp.async.commit_group;" ::: "memory");
}
__device__ __forceinline__ void cp_wait2() {
    asm volatile("cp.async.wait_group 2;" ::: "memory");
}

// ---- per-GT decode (shared by main box-fill and cls key computation) ----
struct GtDec {
    float gx, gy, gw, gh;
    bool  valid;
};
__device__ __forceinline__ GtDec decode_gt(const float* __restrict__ l) {
    GtDec d;
    float l0=l[0], l1=l[1], l2=l[2], l3=l[3], l4=l[4];
    d.valid = (l0 + l1 + l2 + l3 + l4) > 0.0f;
    d.gx = l1*NGRID; d.gy = l2*NGRID; d.gw = l3*NGRID; d.gh = l4*NGRID;
    if (!d.valid) { d.gx = 0.f; d.gy = 0.f; d.gw = 0.f; d.gh = 0.f; }
    return d;
}
__device__ __forceinline__ int best_anchor(float gw, float gh) {
    int best = 0; float bv = -1.0f;
    #pragma unroll
    for (int i = 0; i < 9; i++) {
        float inter = fminf(gw, c_aw[i]) * fminf(gh, c_ah[i]);
        float uni   = gw*gh + c_aw[i]*c_ah[i] - inter;
        float r = inter / uni;
        if (r > bv) { bv = r; best = i; }
    }
    return best;
}

// ---- shared memory union for the fat kernel ----
struct __align__(16) SmemMain {
    unsigned long long W2[(KDIM/2)*16];      // 16384 B  {w_2kp, w_2kp+1} pairs
    float st[4][8][MAIN_THREADS];            // 16384 B (4-stage pipeline)
    float4 Box[NBOX];                        // single batch per block
    float  Area[NBOX];                       // pre-scaled by 7/17
    float  B[15];
    float  red[MAIN_THREADS];
};
struct SmemCls {
    float  xcol[KDIM];
    float  spart[NCH*33];
    float  zfull[NCH];
    float  lred[NCLS];
    float  siou[48];
    float4 gbox[NBOX];
    float  garea[NBOX];                      // pre-scaled by 7/17
    int    skey[NBOX];
    int    sa[NBOX];
    int    shw[NBOX];
};
struct SmemFin {
    float4 r4[MAIN_THREADS];
};
union SmemU { SmemMain m; SmemCls c; SmemFin f; };

// ---- winner path: local GT matching + full 85-channel conv + correction losses ----
__device__ void cls_path(SmemCls* s, int gid,
        const float* __restrict__ xin, const float* __restrict__ labels,
        const float* __restrict__ Wm, const float* __restrict__ bias) {
    int tid = threadIdx.x;
    int b = gid / NBOX, n = gid % NBOX;

    // decode all 50 GTs of this batch (threads 0..49)
    if (tid < NBOX) {
        GtDec d = decode_gt(labels + (b*NBOX + tid)*5);
        s->gbox[tid]  = make_float4(d.gx - 0.5f*d.gw, d.gy - 0.5f*d.gh,
                                    d.gx + 0.5f*d.gw, d.gy + 0.5f*d.gh);
        s->garea[tid] = C717 * (d.gw * d.gh);
        int bestb = best_anchor(d.gw, d.gh);
        int a_ = (d.valid && bestb <= 2) ? bestb : -1;
        int gi = (int)floorf(d.gx), gj = (int)floorf(d.gy);
        bool inb = (a_ >= 0) && gi >= 0 && gi < NGRID && gj >= 0 && gj < NGRID;
        s->skey[tid] = inb ? ((a_*NGRID + gj)*NGRID + gi) : (-1 - tid);  // unique negatives
        s->sa[tid]   = a_;
        s->shw[tid]  = gj*NGRID + gi;
    }
    __syncthreads();

    // winner: in-bounds match AND no later GT claims the same cell (last write wins)
    int key = s->skey[n];
    bool winner = (key >= 0);
    for (int m = n + 1; m < NBOX; m++)
        if (s->skey[m] == key) winner = false;
    if (!winner) {
        if (tid == 0) g_corr[gid] = make_float4(0.f, 0.f, 0.f, 0.f);
        return;
    }
    int a  = s->sa[n];
    int hw = s->shw[n];

    const float* src = xin + (size_t)b * KDIM * NCELL + hw;
    s->xcol[tid]       = src[(size_t)tid * NCELL];
    s->xcol[tid + 128] = src[(size_t)(tid + 128) * NCELL];
    __syncthreads();

    int warp = tid >> 5, lane = tid & 31;
    float4 xv0 = *reinterpret_cast<const float4*>(s->xcol + lane*8);
    float4 xv1 = *reinterpret_cast<const float4*>(s->xcol + lane*8 + 4);
    #pragma unroll 2
    for (int cc = 0; cc < 22; cc++) {
        int j = warp*22 + cc;                 // channel within anchor
        if (j < NCH) {
            const float4* wp = reinterpret_cast<const float4*>(
                Wm + (size_t)(a*NCH + j)*KDIM + lane*8);
            float4 wa = wp[0], wb = wp[1];
            float z = wa.x*xv0.x + wa.y*xv0.y + wa.z*xv0.z + wa.w*xv0.w
                    + wb.x*xv1.x + wb.y*xv1.y + wb.z*xv1.z + wb.w*xv1.w;
            s->spart[j*33 + lane] = z;
        }
    }
    __syncthreads();
    if (tid < NCH) {
        float sm = 0.0f;
        #pragma unroll 8
        for (int l = 0; l < 32; l++) sm += s->spart[tid*33 + l];
        s->zfull[tid] = sm + bias[a*NCH + tid];
    }
    __syncthreads();

    // decode (redundant across threads, cheap)
    float x0 = s->zfull[0], x1 = s->zfull[1], x2 = s->zfull[2];
    float x3 = s->zfull[3], x4 = s->zfull[4];
    float fx = (float)(hw % NGRID), fy = (float)(hw / NGRID);
    float sx = sigm(x0), sy = sigm(x1);
    float pw = expf(x2) * c_aw[a];
    float ph = expf(x3) * c_ah[a];
    float px = sx + fx, py = sy + fy;
    float pl = px - 0.5f*pw, pr = px + 0.5f*pw;
    float pt = py - 0.5f*ph, pb = py + 0.5f*ph;
    float cpa = C717 * (pw * ph);

    if (tid < NCLS) {
        float p = sigm(s->zfull[5 + tid]);
        int gtc = (int)labels[gid*5];
        s->lred[tid] = (tid == gtc) ? -safelog(p) : -safelog(1.0f - p);
    } else {
        // threads 80..127: IOU partials over boxes j and j+48
        int j0 = tid - 80;
        float bad = -1e30f;
        #pragma unroll
        for (int rep = 0; rep < 2; rep++) {
            int j = j0 + rep*48;
            if (j < NBOX) {
                float4 g = s->gbox[j];
                float cga = s->garea[j];
                float tlx = fmaxf(pl, g.x);
                float tly = fmaxf(pt, g.y);
                float brx = fminf(pr, g.z);
                float bry = fminf(pb, g.w);
                float iw = fmaxf(brx - tlx, 0.0f);
                float ih = fmaxf(bry - tly, 0.0f);
                bad = fmaxf(bad, fmaf(iw, ih, -cga));
            }
        }
        s->siou[j0] = bad;
    }
    __syncthreads();

    if (tid == 0) {
        float bad = -1e30f;
        #pragma unroll 8
        for (int i = 0; i < 48; i++) bad = fmaxf(bad, s->siou[i]);
        bool noobj = (bad <= cpa);              // bestiou <= 0.7
        float conf = sigm(x4);
        float cobj = -safelog(conf);
        if (noobj) cobj -= -safelog(1.0f - conf);

        const float* l = labels + gid*5;
        float gx = l[1]*NGRID, gy = l[2]*NGRID;
        float gw = l[3]*NGRID, gh = l[4]*NGRID;
        float tx = gx - floorf(gx), ty = gy - floorf(gy);
        float sc = 2.0f - gw*gh * (1.0f/(float)(NGRID*NGRID));
        float cxy = sc * (bce(sx, tx) + bce(sy, ty));
        float tw = logf(gw / c_aw[a] + 1e-16f);
        float th = logf(gh / c_ah[a] + 1e-16f);
        float rs = sqrtf(sc);
        float dw = x2*rs - tw*rs, dh = x3*rs - th*rs;
        float cwh = 0.5f * (dw*dw + dh*dh);

        float ccls = 0.0f;
        #pragma unroll 8
        for (int i = 0; i < NCLS; i++) ccls += s->lred[i];
        g_corr[gid] = make_float4(cxy, cwh, cobj, ccls);
    }
}

// ---- main path: 4-stage cp.async 15-ch GEMM (k-paired f32x2) + noobj loss ----
__device__ void main_path(SmemMain* s, int mbid,
        const float* __restrict__ xin, const float* __restrict__ labels,
        const float* __restrict__ Wm, const float* __restrict__ bias) {
    int tid = threadIdx.x;
    int b   = mbid / BLK_PER_B;
    int blk = mbid - b*BLK_PER_B;
    int hw0 = blk * 128;
    int act = NCELL - hw0; if (act > 128) act = 128;   // 128, or 16 for tail block

    // pack weight k-pairs straight from Wm (L2-hot)
    #pragma unroll
    for (int ii = 0; ii < 16; ii++) {
        int i = tid + ii*MAIN_THREADS;                 // 0..2047
        int kp = i >> 4, o = i & 15;
        unsigned long long v = 0ull;
        if (o < 15) {
            int row = (o/5)*NCH + (o%5);
            float2 w = *reinterpret_cast<const float2*>(Wm + row*KDIM + 2*kp);
            v = pack2(w.x, w.y);
        }
        s->W2[i] = v;
    }
    if (tid < 15) s->B[tid] = bias[(tid/5)*NCH + (tid%5)];
    if (tid < NBOX) {
        GtDec d = decode_gt(labels + (b*NBOX + tid)*5);
        s->Box[tid]  = make_float4(d.gx - 0.5f*d.gw, d.gy - 0.5f*d.gh,
                                   d.gx + 0.5f*d.gw, d.gy + 0.5f*d.gh);
        s->Area[tid] = C717 * (d.gw * d.gh);
    }

    // cp.async chunk mapping: each thread owns chunks (r0,col) and (r0+4,col)
    int r0  = tid >> 5;                    // 0..3
    int col = tid & 31;                    // 16B chunk within a 512B k-row
    bool cvalid = (col * 16) < (act * 4);
    const char* gA = (const char*)xin
        + ((size_t)(b*KDIM + r0) * NCELL + hw0) * 4 + (size_t)col * 16;
    const char* gB = gA + (size_t)4 * NCELL * 4;
    const size_t stride8 = (size_t)8 * NCELL * 4;      // advance 8 k-rows
    uint32_t dA = (uint32_t)__cvta_generic_to_shared(&s->st[0][0][0]) + r0*512 + col*16;
    uint32_t dB = dA + 4*512;

    // prologue: stages 0..2 in flight (groups g0,g1,g2)
    #pragma unroll
    for (int st0 = 0; st0 < 3; st0++) {
        if (cvalid) {
            cp16(dA + st0*4096, gA);
            cp16(dB + st0*4096, gB);
        }
        cp_commit();
        gA += stride8; gB += stride8;
    }

    __syncthreads();   // W2 / Box / B visible

    unsigned long long acc[15];
    #pragma unroll
    for (int o = 0; o < 15; o++) acc[o] = pack2(s->B[o], 0.0f);   // bias in lo half

    #pragma unroll 4
    for (int kb = 0; kb < 32; kb++) {
        cp_wait2();           // group g_kb complete (exactly <=2 newer groups pending)
        __syncthreads();      // stage kb visible; all threads past stage kb-1 reads
        int bufi = kb & 3;
        #pragma unroll
        for (int i = 0; i < 4; i++) {
            float lo = s->st[bufi][2*i][tid];
            float hi = s->st[bufi][2*i + 1][tid];
            unsigned long long x2 = pack2(lo, hi);
            int kp = kb*4 + i;
            const ulonglong2* wp = reinterpret_cast<const ulonglong2*>(s->W2 + kp*16);
            #pragma unroll
            for (int j = 0; j < 7; j++) {
                ulonglong2 w2 = wp[j];
                fma2(acc[2*j],   w2.x, x2);
                fma2(acc[2*j+1], w2.y, x2);
            }
            fma2(acc[14], s->W2[kp*16 + 14], x2);
        }
        // stage kb+3 writes buffer (kb+3)&3 == (kb-1)&3 — safe: the sync above
        // proves every thread finished reading it in iteration kb-1.
        if (kb + 3 < 32) {
            int st3 = (kb + 3) & 3;
            if (cvalid) {
                cp16(dA + st3*4096, gA);
                cp16(dB + st3*4096, gB);
            }
            gA += stride8; gB += stride8;
        }
        cp_commit();          // UNCONDITIONAL: keeps wait_group arithmetic valid
    }

    float lobj = 0.f;
    if (tid < act) {
        int hw = hw0 + tid;
        float fx = (float)(hw % NGRID);
        float fy = (float)(hw / NGRID);
        float xs[15];
        #pragma unroll
        for (int o = 0; o < 15; o++) {
            float2 u = unpack2(acc[o]);
            xs[o] = u.x + u.y;               // even-k sum (+bias) + odd-k sum
        }
        #pragma unroll
        for (int a = 0; a < 3; a++) {        // anchors outer: fewer live regs
            float sx = sigm(xs[a*5+0]), sy = sigm(xs[a*5+1]);
            float pw = expf(xs[a*5+2]) * c_aw[a];
            float ph = expf(xs[a*5+3]) * c_ah[a];
            float px = sx + fx, py = sy + fy;
            float pl = px - 0.5f*pw, pr = px + 0.5f*pw;
            float pt = py - 0.5f*ph, pb = py + 0.5f*ph;
            float cpa = C717 * (pw * ph);
            float bad = -1e30f;
            #pragma unroll 2
            for (int j = 0; j < NBOX; j++) {
                float4 g = s->Box[j];
                float cga = s->Area[j];
                float tlx = fmaxf(pl, g.x);
                float tly = fmaxf(pt, g.y);
                float brx = fminf(pr, g.z);
                float bry = fminf(pb, g.w);
                float iw = fmaxf(brx - tlx, 0.0f);
                float ih = fmaxf(bry - tly, 0.0f);
                bad = fmaxf(bad, fmaf(iw, ih, -cga));
            }
            if (bad <= cpa) {                     // bestiou <= 0.7
                float conf = sigm(xs[a*5+4]);
                lobj += -safelog(1.0f - conf);
            }
        }
    }

    // single deterministic block reduction (obj only)
    float* sred = s->red;
    sred[tid] = lobj; __syncthreads();
    for (int st = MAIN_THREADS/2; st > 0; st >>= 1) {
        if (tid < st) sred[tid] += sred[tid+st];
        __syncthreads();
    }
    if (tid == 0) g_obj[mbid] = sred[0];
}

// ---- final reduction, run by the last block to finish ----
__device__ void final_path(SmemFin* s, float* __restrict__ out) {
    int tid = threadIdx.x;
    float oxy = 0.f, owh = 0.f, oobj = 0.f, ocls = 0.f;
    for (int i = tid; i < MAIN_BLOCKS; i += MAIN_THREADS) oobj += g_obj[i];
    for (int i = tid; i < NB*NBOX; i += MAIN_THREADS) {
        float4 c = g_corr[i];
        oxy += c.x; owh += c.y; oobj += c.z; ocls += c.w;
    }
    s->r4[tid] = make_float4(oxy, owh, oobj, ocls);
    __syncthreads();
    for (int st = MAIN_THREADS/2; st > 0; st >>= 1) {
        if (tid < st) {
            float4 a = s->r4[tid], b = s->r4[tid+st];
            s->r4[tid] = make_float4(a.x+b.x, a.y+b.y, a.z+b.z, a.w+b.w);
        }
        __syncthreads();
    }
    if (tid == 0) {
        float4 r = s->r4[0];
        out[0] = r.x + r.y + r.z + r.w;
        out[1] = r.x; out[2] = r.y; out[3] = r.z; out[4] = r.w;
        g_count = 0;                       // restore state for next graph replay
    }
}

// ---- THE kernel: main blocks [0,736), winner blocks [736,1536), fused finale ----
__global__ void __launch_bounds__(MAIN_THREADS)
k_fat(const float* __restrict__ xin, const float* __restrict__ labels,
      const float* __restrict__ Wm, const float* __restrict__ bias,
      float* __restrict__ out) {
    __shared__ SmemU su;
    __shared__ bool is_last;
    int bid = blockIdx.x;
    if (bid < MAIN_BLOCKS) {
        main_path(&su.m, bid, xin, labels, Wm, bias);
    } else {
        cls_path(&su.c, bid - MAIN_BLOCKS, xin, labels, Wm, bias);
    }
    // completion counter; last block reduces everything
    __threadfence();
    __syncthreads();
    if (threadIdx.x == 0) {
        int v = atomicAdd(&g_count, 1);
        is_last = (v == FAT_BLOCKS - 1);
    }
    __syncthreads();
    if (is_last) {
        __threadfence();
        final_path(&su.f, out);
    }
}

extern "C" void kernel_launch(void* const* d_in, const int* in_sizes, int n_in,
                              void* d_out, int out_size) {
    const float* xin    = (const float*)d_in[0];
    const float* labels = (const float*)d_in[1];
    const float* W      = (const float*)d_in[2];
    const float* b      = (const float*)d_in[3];
    float* out = (float*)d_out;

    k_fat<<<FAT_BLOCKS, MAIN_THREADS>>>(xin, labels, W, b, out);
}

// round 15
// speedup vs baseline: 1.1330x; 1.1269x over previous
#include <cuda_runtime.h>
#include <math.h>
#include <stdint.h>

#define NB     16
#define NA3    3
#define NGRID  76
#define NCELL  (NGRID*NGRID)        // 5776
#define CELLS  (NB*NCELL)           // 92416
#define KDIM   256
#define NBOX   50
#define NCLS   80
#define NCH    85                   // 5 + 80

#define MAIN_THREADS      128
#define BLK_PER_B         46                          // ceil(5776/128); last block has 16 cells
#define MAIN_BLOCKS       (NB*BLK_PER_B)              // 736
#define CLS_BLOCKS        (NB*NBOX)                   // 800
#define FAT_BLOCKS        (MAIN_BLOCKS + CLS_BLOCKS)  // 1536

#define C717  0.41176470588235294f   // 7/17, same literal everywhere
#define WSTRIDE 18                    // padded u64 stride for W2 rows (16B-aligned)

// ---- device scratch (no allocation allowed) ----
__device__ float  g_obj[MAIN_BLOCKS];       // per-main-block noobj loss partial
__device__ float4 g_corr[NB*NBOX];          // per-GT correction (xy, wh, obj, cls)
__device__ int    g_count = 0;              // completed-block counter (reset by finale)

// ALL_ANCHORS = ANCHORS_PX / 8
__constant__ float c_aw[9] = {1.25f, 2.0f, 4.125f, 3.75f, 7.75f, 7.375f, 14.5f, 19.5f, 46.625f};
__constant__ float c_ah[9] = {1.625f, 3.75f, 2.875f, 7.625f, 5.625f, 14.875f, 11.25f, 24.75f, 40.75f};

__device__ __forceinline__ float safelog(float p) {
    return fmaxf(logf(fmaxf(p, 1e-12f)), -100.0f);
}
__device__ __forceinline__ float bce(float p, float t) {
    return -(t * safelog(p) + (1.0f - t) * safelog(1.0f - p));
}
__device__ __forceinline__ float sigm(float x) {
    return 1.0f / (1.0f + expf(-x));
}
__device__ __forceinline__ unsigned long long pack2(float lo, float hi) {
    unsigned long long r;
    asm("mov.b64 %0, {%1, %2};" : "=l"(r) : "f"(lo), "f"(hi));
    return r;
}
__device__ __forceinline__ float2 unpack2(unsigned long long p) {
    float2 q;
    asm("mov.b64 {%0, %1}, %2;" : "=f"(q.x), "=f"(q.y) : "l"(p));
    return q;
}
__device__ __forceinline__ void fma2(unsigned long long& d, unsigned long long a, unsigned long long b) {
    asm("fma.rn.f32x2 %0, %1, %2, %0;" : "+l"(d) : "l"(a), "l"(b));
}
__device__ __forceinline__ void cp16(uint32_t dst, const void* src) {
    asm volatile("cp.async.cg.shared.global [%0], [%1], 16;" :: "r"(dst), "l"(src));
}
__device__ __forceinline__ void cp_commit() {
    asm volatile("cp.async.commit_group;" ::: "memory");
}
__device__ __forceinline__ void cp_wait2() {
    asm volatile("cp.async.wait_group 2;" ::: "memory");
}

// ---- per-GT decode ----
struct GtDec {
    float gx, gy, gw, gh;
    bool  valid;
};
__device__ __forceinline__ GtDec decode_gt(const float* __restrict__ l) {
    GtDec d;
    float l0=l[0], l1=l[1], l2=l[2], l3=l[3], l4=l[4];
    d.valid = (l0 + l1 + l2 + l3 + l4) > 0.0f;
    d.gx = l1*NGRID; d.gy = l2*NGRID; d.gw = l3*NGRID; d.gh = l4*NGRID;
    if (!d.valid) { d.gx = 0.f; d.gy = 0.f; d.gw = 0.f; d.gh = 0.f; }
    return d;
}
__device__ __forceinline__ int best_anchor(float gw, float gh) {
    int best = 0; float bv = -1.0f;
    #pragma unroll
    for (int i = 0; i < 9; i++) {
        float inter = fminf(gw, c_aw[i]) * fminf(gh, c_ah[i]);
        float uni   = gw*gh + c_aw[i]*c_ah[i] - inter;
        float r = inter / uni;
        if (r > bv) { bv = r; best = i; }
    }
    return best;
}

// ---- shared memory union for the fat kernel ----
struct __align__(16) SmemMain {
    unsigned long long W2[KDIM/2*WSTRIDE];   // 18432 B  {w_2kp, w_2kp+1} pairs, padded rows
    float st[4][8][MAIN_THREADS];            // 16384 B (4-stage pipeline, warp-column-owned)
    float4 Box[NBOX];
    float  Area[NBOX];                       // pre-scaled by 7/17
    float  B[15];
    float  red[MAIN_THREADS];
};
struct SmemCls {
    float  xcol[KDIM];
    float  spart[NCH*33];
    float  zfull[NCH];
    float  lred[NCLS];
    float  siou[48];
    float4 gbox[NBOX];
    float  garea[NBOX];                      // pre-scaled by 7/17
    int    skey[NBOX];
    int    sa[NBOX];
    int    shw[NBOX];
};
struct SmemFin {
    float4 r4[MAIN_THREADS];
};
union SmemU { SmemMain m; SmemCls c; SmemFin f; };

// ---- winner path: local GT matching + full 85-channel conv + correction losses ----
__device__ void cls_path(SmemCls* s, int gid,
        const float* __restrict__ xin, const float* __restrict__ labels,
        const float* __restrict__ Wm, const float* __restrict__ bias) {
    int tid = threadIdx.x;
    int b = gid / NBOX, n = gid % NBOX;

    // decode all 50 GTs of this batch (threads 0..49)
    if (tid < NBOX) {
        GtDec d = decode_gt(labels + (b*NBOX + tid)*5);
        s->gbox[tid]  = make_float4(d.gx - 0.5f*d.gw, d.gy - 0.5f*d.gh,
                                    d.gx + 0.5f*d.gw, d.gy + 0.5f*d.gh);
        s->garea[tid] = C717 * (d.gw * d.gh);
        int bestb = best_anchor(d.gw, d.gh);
        int a_ = (d.valid && bestb <= 2) ? bestb : -1;
        int gi = (int)floorf(d.gx), gj = (int)floorf(d.gy);
        bool inb = (a_ >= 0) && gi >= 0 && gi < NGRID && gj >= 0 && gj < NGRID;
        s->skey[tid] = inb ? ((a_*NGRID + gj)*NGRID + gi) : (-1 - tid);  // unique negatives
        s->sa[tid]   = a_;
        s->shw[tid]  = gj*NGRID + gi;
    }
    __syncthreads();

    // winner: in-bounds match AND no later GT claims the same cell (last write wins)
    int key = s->skey[n];
    bool winner = (key >= 0);
    for (int m = n + 1; m < NBOX; m++)
        if (s->skey[m] == key) winner = false;
    if (!winner) {
        if (tid == 0) g_corr[gid] = make_float4(0.f, 0.f, 0.f, 0.f);
        return;
    }
    int a  = s->sa[n];
    int hw = s->shw[n];

    const float* src = xin + (size_t)b * KDIM * NCELL + hw;
    s->xcol[tid]       = src[(size_t)tid * NCELL];
    s->xcol[tid + 128] = src[(size_t)(tid + 128) * NCELL];
    __syncthreads();

    int warp = tid >> 5, lane = tid & 31;
    float4 xv0 = *reinterpret_cast<const float4*>(s->xcol + lane*8);
    float4 xv1 = *reinterpret_cast<const float4*>(s->xcol + lane*8 + 4);
    #pragma unroll 2
    for (int cc = 0; cc < 22; cc++) {
        int j = warp*22 + cc;                 // channel within anchor
        if (j < NCH) {
            const float4* wp = reinterpret_cast<const float4*>(
                Wm + (size_t)(a*NCH + j)*KDIM + lane*8);
            float4 wa = wp[0], wb = wp[1];
            float z = wa.x*xv0.x + wa.y*xv0.y + wa.z*xv0.z + wa.w*xv0.w
                    + wb.x*xv1.x + wb.y*xv1.y + wb.z*xv1.z + wb.w*xv1.w;
            s->spart[j*33 + lane] = z;
        }
    }
    __syncthreads();
    if (tid < NCH) {
        float sm = 0.0f;
        #pragma unroll 8
        for (int l = 0; l < 32; l++) sm += s->spart[tid*33 + l];
        s->zfull[tid] = sm + bias[a*NCH + tid];
    }
    __syncthreads();

    // decode (redundant across threads, cheap)
    float x0 = s->zfull[0], x1 = s->zfull[1], x2 = s->zfull[2];
    float x3 = s->zfull[3], x4 = s->zfull[4];
    float fx = (float)(hw % NGRID), fy = (float)(hw / NGRID);
    float sx = sigm(x0), sy = sigm(x1);
    float pw = expf(x2) * c_aw[a];
    float ph = expf(x3) * c_ah[a];
    float px = sx + fx, py = sy + fy;
    float pl = px - 0.5f*pw, pr = px + 0.5f*pw;
    float pt = py - 0.5f*ph, pb = py + 0.5f*ph;
    float cpa = C717 * (pw * ph);

    if (tid < NCLS) {
        float p = sigm(s->zfull[5 + tid]);
        int gtc = (int)labels[gid*5];
        s->lred[tid] = (tid == gtc) ? -safelog(p) : -safelog(1.0f - p);
    } else {
        // threads 80..127: IOU partials over boxes j and j+48
        int j0 = tid - 80;
        float bad = -1e30f;
        #pragma unroll
        for (int rep = 0; rep < 2; rep++) {
            int j = j0 + rep*48;
            if (j < NBOX) {
                float4 g = s->gbox[j];
                float cga = s->garea[j];
                float tlx = fmaxf(pl, g.x);
                float tly = fmaxf(pt, g.y);
                float brx = fminf(pr, g.z);
                float bry = fminf(pb, g.w);
                float iw = fmaxf(brx - tlx, 0.0f);
                float ih = fmaxf(bry - tly, 0.0f);
                bad = fmaxf(bad, fmaf(iw, ih, -cga));
            }
        }
        s->siou[j0] = bad;
    }
    __syncthreads();

    if (tid == 0) {
        float bad = -1e30f;
        #pragma unroll 8
        for (int i = 0; i < 48; i++) bad = fmaxf(bad, s->siou[i]);
        bool noobj = (bad <= cpa);              // bestiou <= 0.7
        float conf = sigm(x4);
        float cobj = -safelog(conf);
        if (noobj) cobj -= -safelog(1.0f - conf);

        const float* l = labels + gid*5;
        float gx = l[1]*NGRID, gy = l[2]*NGRID;
        float gw = l[3]*NGRID, gh = l[4]*NGRID;
        float tx = gx - floorf(gx), ty = gy - floorf(gy);
        float sc = 2.0f - gw*gh * (1.0f/(float)(NGRID*NGRID));
        float cxy = sc * (bce(sx, tx) + bce(sy, ty));
        float tw = logf(gw / c_aw[a] + 1e-16f);
        float th = logf(gh / c_ah[a] + 1e-16f);
        float rs = sqrtf(sc);
        float dw = x2*rs - tw*rs, dh = x3*rs - th*rs;
        float cwh = 0.5f * (dw*dw + dh*dh);

        float ccls = 0.0f;
        #pragma unroll 8
        for (int i = 0; i < NCLS; i++) ccls += s->lred[i];
        g_corr[gid] = make_float4(cxy, cwh, cobj, ccls);
    }
}

// ---- main path: warp-private 4-stage cp.async GEMM (k-paired f32x2) + noobj loss ----
__device__ void main_path(SmemMain* s, int mbid,
        const float* __restrict__ xin, const float* __restrict__ labels,
        const float* __restrict__ Wm, const float* __restrict__ bias) {
    int tid = threadIdx.x;
    int b   = mbid / BLK_PER_B;
    int blk = mbid - b*BLK_PER_B;
    int hw0 = blk * 128;
    int act = NCELL - hw0; if (act > 128) act = 128;   // 128, or 16 for tail block

    // weight pack: o-outer/kp-inner -> 15 fully-coalesced float2 row reads,
    // stores into padded stride-18 layout (<=4-way STS conflict)
    #pragma unroll
    for (int o = 0; o < 15; o++) {
        int row = (o/5)*NCH + (o%5);
        float2 w = *reinterpret_cast<const float2*>(Wm + row*KDIM + 2*tid);
        s->W2[tid*WSTRIDE + o] = pack2(w.x, w.y);
    }
    if (tid < 15) s->B[tid] = bias[(tid/5)*NCH + (tid%5)];
    if (tid < NBOX) {
        GtDec d = decode_gt(labels + (b*NBOX + tid)*5);
        s->Box[tid]  = make_float4(d.gx - 0.5f*d.gw, d.gy - 0.5f*d.gh,
                                   d.gx + 0.5f*d.gw, d.gy + 0.5f*d.gh);
        s->Area[tid] = C717 * (d.gw * d.gh);
    }

    // warp-private staging: warp w owns cells [32w, 32w+32)
    int warp = tid >> 5, lane = tid & 31;
    int r1   = lane >> 3;                 // rows r1 and r1+4
    int cell = warp*32 + (lane & 7)*4;    // 16B chunk = 4 cells
    bool cvalid = cell < act;
    const char* gA = (const char*)(xin
        + ((size_t)(b*KDIM + r1) * NCELL + hw0 + cell)) ;
    const char* gB = (const char*)(xin
        + ((size_t)(b*KDIM + r1 + 4) * NCELL + hw0 + cell));
    const size_t stride8 = (size_t)8 * NCELL * 4;      // advance 8 k-rows (bytes)
    uint32_t dA = (uint32_t)__cvta_generic_to_shared(&s->st[0][0][0]) + r1*512 + cell*4;
    uint32_t dB = dA + 4*512;

    // prologue: stages 0..2 in flight (groups g0,g1,g2)
    #pragma unroll
    for (int st0 = 0; st0 < 3; st0++) {
        if (cvalid) {
            cp16(dA + st0*4096, gA);
            cp16(dB + st0*4096, gB);
        }
        cp_commit();
        gA += stride8; gB += stride8;
    }

    __syncthreads();   // W2 / Box / B visible to all warps

    unsigned long long acc[15];
    #pragma unroll
    for (int o = 0; o < 15; o++) acc[o] = pack2(s->B[o], 0.0f);   // bias in lo half

    #pragma unroll 4
    for (int kb = 0; kb < 32; kb++) {
        cp_wait2();           // own groups <=2 pending => group kb complete
        __syncwarp();         // all warp-mates past their waits => their copies done
        int bufi = kb & 3;
        #pragma unroll
        for (int i = 0; i < 4; i++) {
            float lo = s->st[bufi][2*i][tid];
            float hi = s->st[bufi][2*i + 1][tid];
            unsigned long long x2 = pack2(lo, hi);
            int kp = kb*4 + i;
            const ulonglong2* wp = reinterpret_cast<const ulonglong2*>(s->W2 + kp*WSTRIDE);
            #pragma unroll
            for (int j = 0; j < 7; j++) {
                ulonglong2 w2 = wp[j];
                fma2(acc[2*j],   w2.x, x2);
                fma2(acc[2*j+1], w2.y, x2);
            }
            fma2(acc[14], s->W2[kp*WSTRIDE + 14], x2);
        }
        // stage kb+3 writes buffer (kb-1)&3: this warp's reads of it finished in
        // iteration kb-1, ordered by the __syncwarp at the top of this iteration.
        if (kb + 3 < 32) {
            int st3 = (kb + 3) & 3;
            if (cvalid) {
                cp16(dA + st3*4096, gA);
                cp16(dB + st3*4096, gB);
            }
            gA += stride8; gB += stride8;
        }
        cp_commit();          // UNCONDITIONAL: keeps wait_group arithmetic valid
    }

    float lobj = 0.f;
    if (tid < act) {
        int hw = hw0 + tid;
        float fx = (float)(hw % NGRID);
        float fy = (float)(hw / NGRID);
        float xs[15];
        #pragma unroll
        for (int o = 0; o < 15; o++) {
            float2 u = unpack2(acc[o]);
            xs[o] = u.x + u.y;               // even-k sum (+bias) + odd-k sum
        }
        #pragma unroll
        for (int a = 0; a < 3; a++) {        // anchors outer: fewer live regs
            float sx = sigm(xs[a*5+0]), sy = sigm(xs[a*5+1]);
            float pw = expf(xs[a*5+2]) * c_aw[a];
            float ph = expf(xs[a*5+3]) * c_ah[a];
            float px = sx + fx, py = sy + fy;
            float pl = px - 0.5f*pw, pr = px + 0.5f*pw;
            float pt = py - 0.5f*ph, pb = py + 0.5f*ph;
            float cpa = C717 * (pw * ph);
            float bad = -1e30f;
            #pragma unroll 2
            for (int j = 0; j < NBOX; j++) {
                float4 g = s->Box[j];
                float cga = s->Area[j];
                float tlx = fmaxf(pl, g.x);
                float tly = fmaxf(pt, g.y);
                float brx = fminf(pr, g.z);
                float bry = fminf(pb, g.w);
                float iw = fmaxf(brx - tlx, 0.0f);
                float ih = fmaxf(bry - tly, 0.0f);
                bad = fmaxf(bad, fmaf(iw, ih, -cga));
            }
            if (bad <= cpa) {                     // bestiou <= 0.7
                float conf = sigm(xs[a*5+4]);
                lobj += -safelog(1.0f - conf);
            }
        }
    }

    // single deterministic block reduction (obj only)
    float* sred = s->red;
    __syncthreads();                       // re-converge warps before smem reuse
    sred[tid] = lobj; __syncthreads();
    for (int st = MAIN_THREADS/2; st > 0; st >>= 1) {
        if (tid < st) sred[tid] += sred[tid+st];
        __syncthreads();
    }
    if (tid == 0) g_obj[mbid] = sred[0];
}

// ---- final reduction, run by the last block to finish ----
__device__ void final_path(SmemFin* s, float* __restrict__ out) {
    int tid = threadIdx.x;
    float oxy = 0.f, owh = 0.f, oobj = 0.f, ocls = 0.f;
    for (int i = tid; i < MAIN_BLOCKS; i += MAIN_THREADS) oobj += g_obj[i];
    for (int i = tid; i < NB*NBOX; i += MAIN_THREADS) {
        float4 c = g_corr[i];
        oxy += c.x; owh += c.y; oobj += c.z; ocls += c.w;
    }
    s->r4[tid] = make_float4(oxy, owh, oobj, ocls);
    __syncthreads();
    for (int st = MAIN_THREADS/2; st > 0; st >>= 1) {
        if (tid < st) {
            float4 a = s->r4[tid], b = s->r4[tid+st];
            s->r4[tid] = make_float4(a.x+b.x, a.y+b.y, a.z+b.z, a.w+b.w);
        }
        __syncthreads();
    }
    if (tid == 0) {
        float4 r = s->r4[0];
        out[0] = r.x + r.y + r.z + r.w;
        out[1] = r.x; out[2] = r.y; out[3] = r.z; out[4] = r.w;
        g_count = 0;                       // restore state for next graph replay
    }
}

// ---- THE kernel: main blocks [0,736), winner blocks [736,1536), fused finale ----
__global__ void __launch_bounds__(MAIN_THREADS)
k_fat(const float* __restrict__ xin, const float* __restrict__ labels,
      const float* __restrict__ Wm, const float* __restrict__ bias,
      float* __restrict__ out) {
    __shared__ SmemU su;
    __shared__ bool is_last;
    int bid = blockIdx.x;
    if (bid < MAIN_BLOCKS) {
        main_path(&su.m, bid, xin, labels, Wm, bias);
    } else {
        cls_path(&su.c, bid - MAIN_BLOCKS, xin, labels, Wm, bias);
    }
    // completion counter; last block reduces everything
    __threadfence();
    __syncthreads();
    if (threadIdx.x == 0) {
        int v = atomicAdd(&g_count, 1);
        is_last = (v == FAT_BLOCKS - 1);
    }
    __syncthreads();
    if (is_last) {
        __threadfence();
        final_path(&su.f, out);
    }
}

extern "C" void kernel_launch(void* const* d_in, const int* in_sizes, int n_in,
                              void* d_out, int out_size) {
    const float* xin    = (const float*)d_in[0];
    const float* labels = (const float*)d_in[1];
    const float* W      = (const float*)d_in[2];
    const float* b      = (const float*)d_in[3];
    float* out = (float*)d_out;

    k_fat<<<FAT_BLOCKS, MAIN_THREADS>>>(xin, labels, W, b, out);
}

// round 17
// speedup vs baseline: 1.1990x; 1.0583x over previous
#include <cuda_runtime.h>
#include <math.h>
#include <stdint.h>

#define NB     16
#define NA3    3
#define NGRID  76
#define NCELL  (NGRID*NGRID)        // 5776
#define CELLS  (NB*NCELL)           // 92416
#define KDIM   256
#define NBOX   50
#define NCLS   80
#define NCH    85                   // 5 + 80

#define MAIN_THREADS      128
#define BLK_PER_B         46                          // ceil(5776/128); last block has 16 cells
#define MAIN_BLOCKS       (NB*BLK_PER_B)              // 736
#define CLS_BLOCKS        (NB*NBOX)                   // 800
#define FAT_BLOCKS        (MAIN_BLOCKS + CLS_BLOCKS)  // 1536

#define C717  0.41176470588235294f   // 7/17, same literal everywhere

#define STROW  136                   // padded floats per k-row in a stage (conflict-free A frags)
#define STG_F  (8*STROW)             // 1088 floats per stage
#define STG_B  (STG_F*4)             // 4352 bytes per stage

// ---- device scratch (no allocation allowed) ----
__device__ float  g_obj[MAIN_BLOCKS];       // per-main-block noobj loss partial
__device__ float4 g_corr[NB*NBOX];          // per-GT correction (xy, wh, obj, cls)
__device__ int    g_count = 0;              // completed-block counter (reset by finale)

// ALL_ANCHORS = ANCHORS_PX / 8
__constant__ float c_aw[9] = {1.25f, 2.0f, 4.125f, 3.75f, 7.75f, 7.375f, 14.5f, 19.5f, 46.625f};
__constant__ float c_ah[9] = {1.625f, 3.75f, 2.875f, 7.625f, 5.625f, 14.875f, 11.25f, 24.75f, 40.75f};

__device__ __forceinline__ float safelog(float p) {
    return fmaxf(logf(fmaxf(p, 1e-12f)), -100.0f);
}
__device__ __forceinline__ float bce(float p, float t) {
    return -(t * safelog(p) + (1.0f - t) * safelog(1.0f - p));
}
__device__ __forceinline__ float sigm(float x) {
    return 1.0f / (1.0f + expf(-x));
}
__device__ __forceinline__ uint32_t tf32_of(float x) {
    uint32_t r;
    asm("cvt.rna.tf32.f32 %0, %1;" : "=r"(r) : "f"(x));
    return r;
}
__device__ __forceinline__ void mma_tf32(float c[4], uint32_t a0, uint32_t a1,
                                         uint32_t a2, uint32_t a3,
                                         uint32_t b0, uint32_t b1) {
    asm volatile(
        "mma.sync.aligned.m16n8k8.row.col.f32.tf32.tf32.f32 "
        "{%0,%1,%2,%3}, {%4,%5,%6,%7}, {%8,%9}, {%0,%1,%2,%3};"
        : "+f"(c[0]), "+f"(c[1]), "+f"(c[2]), "+f"(c[3])
        : "r"(a0), "r"(a1), "r"(a2), "r"(a3), "r"(b0), "r"(b1));
}
__device__ __forceinline__ void cp16(uint32_t dst, const void* src) {
    asm volatile("cp.async.cg.shared.global [%0], [%1], 16;" :: "r"(dst), "l"(src));
}
__device__ __forceinline__ void cp_commit() {
    asm volatile("cp.async.commit_group;" ::: "memory");
}
__device__ __forceinline__ void cp_wait2() {
    asm volatile("cp.async.wait_group 2;" ::: "memory");
}
__device__ __forceinline__ void sts64(uint32_t addr, float x, float y) {
    asm volatile("st.shared.v2.f32 [%0], {%1, %2};" :: "r"(addr), "f"(x), "f"(y) : "memory");
}
__device__ __forceinline__ uint32_t smem_u32(const void* p) {
    return (uint32_t)__cvta_generic_to_shared(p);
}

// ---- per-GT decode ----
struct GtDec {
    float gx, gy, gw, gh;
    bool  valid;
};
__device__ __forceinline__ GtDec decode_gt(const float* __restrict__ l) {
    GtDec d;
    float l0=l[0], l1=l[1], l2=l[2], l3=l[3], l4=l[4];
    d.valid = (l0 + l1 + l2 + l3 + l4) > 0.0f;
    d.gx = l1*NGRID; d.gy = l2*NGRID; d.gw = l3*NGRID; d.gh = l4*NGRID;
    if (!d.valid) { d.gx = 0.f; d.gy = 0.f; d.gw = 0.f; d.gh = 0.f; }
    return d;
}
__device__ __forceinline__ int best_anchor(float gw, float gh) {
    int best = 0; float bv = -1.0f;
    #pragma unroll
    for (int i = 0; i < 9; i++) {
        float inter = fminf(gw, c_aw[i]) * fminf(gh, c_ah[i]);
        float uni   = gw*gh + c_aw[i]*c_ah[i] - inter;
        float r = inter / uni;
        if (r > bv) { bv = r; best = i; }
    }
    return best;
}

// ---- shared memory ----
struct __align__(16) SmemMain {
    float st[4][8][STROW];     // 17408 B staging; reused as D[128][18] after k-loop
    float Wb[KDIM][16];        // 16384 B, tf32-converted weights (ch 15 zero)
    float4 Box[NBOX];
    float  Area[NBOX];         // pre-scaled by 7/17
    float  Bv[16];
    float  red[MAIN_THREADS];
};
struct SmemCls {
    float  xcol[KDIM];
    float  spart[NCH*33];
    float  zfull[NCH];
    float  lred[NCLS];
    float  siou[48];
    float4 gbox[NBOX];
    float  garea[NBOX];
    int    skey[NBOX];
    int    sa[NBOX];
    int    shw[NBOX];
};
struct SmemFin {
    float4 r4[MAIN_THREADS];
};
union SmemU { SmemMain m; SmemCls c; SmemFin f; };

// ---- winner path: local GT matching + full 85-channel conv (fp32) + corrections ----
__device__ void cls_path(SmemCls* s, int gid,
        const float* __restrict__ xin, const float* __restrict__ labels,
        const float* __restrict__ Wm, const float* __restrict__ bias) {
    int tid = threadIdx.x;
    int b = gid / NBOX, n = gid % NBOX;

    if (tid < NBOX) {
        GtDec d = decode_gt(labels + (b*NBOX + tid)*5);
        s->gbox[tid]  = make_float4(d.gx - 0.5f*d.gw, d.gy - 0.5f*d.gh,
                                    d.gx + 0.5f*d.gw, d.gy + 0.5f*d.gh);
        s->garea[tid] = C717 * (d.gw * d.gh);
        int bestb = best_anchor(d.gw, d.gh);
        int a_ = (d.valid && bestb <= 2) ? bestb : -1;
        int gi = (int)floorf(d.gx), gj = (int)floorf(d.gy);
        bool inb = (a_ >= 0) && gi >= 0 && gi < NGRID && gj >= 0 && gj < NGRID;
        s->skey[tid] = inb ? ((a_*NGRID + gj)*NGRID + gi) : (-1 - tid);
        s->sa[tid]   = a_;
        s->shw[tid]  = gj*NGRID + gi;
    }
    __syncthreads();

    int key = s->skey[n];
    bool winner = (key >= 0);
    for (int m = n + 1; m < NBOX; m++)
        if (s->skey[m] == key) winner = false;
    if (!winner) {
        if (tid == 0) g_corr[gid] = make_float4(0.f, 0.f, 0.f, 0.f);
        return;
    }
    int a  = s->sa[n];
    int hw = s->shw[n];

    const float* src = xin + (size_t)b * KDIM * NCELL + hw;
    s->xcol[tid]       = src[(size_t)tid * NCELL];
    s->xcol[tid + 128] = src[(size_t)(tid + 128) * NCELL];
    __syncthreads();

    int warp = tid >> 5, lane = tid & 31;
    float4 xv0 = *reinterpret_cast<const float4*>(s->xcol + lane*8);
    float4 xv1 = *reinterpret_cast<const float4*>(s->xcol + lane*8 + 4);
    #pragma unroll 2
    for (int cc = 0; cc < 22; cc++) {
        int j = warp*22 + cc;
        if (j < NCH) {
            const float4* wp = reinterpret_cast<const float4*>(
                Wm + (size_t)(a*NCH + j)*KDIM + lane*8);
            float4 wa = wp[0], wb = wp[1];
            float z = wa.x*xv0.x + wa.y*xv0.y + wa.z*xv0.z + wa.w*xv0.w
                    + wb.x*xv1.x + wb.y*xv1.y + wb.z*xv1.z + wb.w*xv1.w;
            s->spart[j*33 + lane] = z;
        }
    }
    __syncthreads();
    if (tid < NCH) {
        float sm = 0.0f;
        #pragma unroll 8
        for (int l = 0; l < 32; l++) sm += s->spart[tid*33 + l];
        s->zfull[tid] = sm + bias[a*NCH + tid];
    }
    __syncthreads();

    float x0 = s->zfull[0], x1 = s->zfull[1], x2 = s->zfull[2];
    float x3 = s->zfull[3], x4 = s->zfull[4];
    float fx = (float)(hw % NGRID), fy = (float)(hw / NGRID);
    float sx = sigm(x0), sy = sigm(x1);
    float pw = expf(x2) * c_aw[a];
    float ph = expf(x3) * c_ah[a];
    float px = sx + fx, py = sy + fy;
    float pl = px - 0.5f*pw, pr = px + 0.5f*pw;
    float pt = py - 0.5f*ph, pb = py + 0.5f*ph;
    float cpa = C717 * (pw * ph);

    if (tid < NCLS) {
        float p = sigm(s->zfull[5 + tid]);
        int gtc = (int)labels[gid*5];
        s->lred[tid] = (tid == gtc) ? -safelog(p) : -safelog(1.0f - p);
    } else {
        int j0 = tid - 80;
        float bad = -1e30f;
        #pragma unroll
        for (int rep = 0; rep < 2; rep++) {
            int j = j0 + rep*48;
            if (j < NBOX) {
                float4 g = s->gbox[j];
                float cga = s->garea[j];
                float tlx = fmaxf(pl, g.x);
                float tly = fmaxf(pt, g.y);
                float brx = fminf(pr, g.z);
                float bry = fminf(pb, g.w);
                float iw = fmaxf(brx - tlx, 0.0f);
                float ih = fmaxf(bry - tly, 0.0f);
                bad = fmaxf(bad, fmaf(iw, ih, -cga));
            }
        }
        s->siou[j0] = bad;
    }
    __syncthreads();

    if (tid == 0) {
        float bad = -1e30f;
        #pragma unroll 8
        for (int i = 0; i < 48; i++) bad = fmaxf(bad, s->siou[i]);
        bool noobj = (bad <= cpa);
        float conf = sigm(x4);
        float cobj = -safelog(conf);
        if (noobj) cobj -= -safelog(1.0f - conf);

        const float* l = labels + gid*5;
        float gx = l[1]*NGRID, gy = l[2]*NGRID;
        float gw = l[3]*NGRID, gh = l[4]*NGRID;
        float tx = gx - floorf(gx), ty = gy - floorf(gy);
        float sc = 2.0f - gw*gh * (1.0f/(float)(NGRID*NGRID));
        float cxy = sc * (bce(sx, tx) + bce(sy, ty));
        float tw = logf(gw / c_aw[a] + 1e-16f);
        float th = logf(gh / c_ah[a] + 1e-16f);
        float rs = sqrtf(sc);
        float dw = x2*rs - tw*rs, dh = x3*rs - th*rs;
        float cwh = 0.5f * (dw*dw + dh*dh);

        float ccls = 0.0f;
        #pragma unroll 8
        for (int i = 0; i < NCLS; i++) ccls += s->lred[i];
        g_corr[gid] = make_float4(cxy, cwh, cobj, ccls);
    }
}

// ---- main path: tf32 mma.sync GEMM (M=128, N=16, K=256) + noobj loss ----
__device__ void main_path(SmemMain* s, int mbid,
        const float* __restrict__ xin, const float* __restrict__ labels,
        const float* __restrict__ Wm, const float* __restrict__ bias) {
    int tid = threadIdx.x;
    int warp = tid >> 5, lane = tid & 31;
    int b   = mbid / BLK_PER_B;
    int blk = mbid - b*BLK_PER_B;
    int hw0 = blk * 128;
    int act = NCELL - hw0; if (act > 128) act = 128;

    // Wb fill: ch = tid&15, 32 k per thread, round-to-nearest tf32
    {
        int ch = tid & 15, kg = tid >> 4;
        if (ch < 15) {
            int row = (ch/5)*NCH + (ch%5);
            const float* wsrc = Wm + (size_t)row*KDIM + kg*32;
            #pragma unroll 8
            for (int i = 0; i < 32; i++)
                s->Wb[kg*32 + i][ch] = __uint_as_float(tf32_of(wsrc[i]));
        } else {
            #pragma unroll 8
            for (int i = 0; i < 32; i++)
                s->Wb[kg*32 + i][15] = 0.0f;
        }
    }
    if (tid < 15) s->Bv[tid] = bias[(tid/5)*NCH + (tid%5)];
    if (tid < NBOX) {
        GtDec d = decode_gt(labels + (b*NBOX + tid)*5);
        s->Box[tid]  = make_float4(d.gx - 0.5f*d.gw, d.gy - 0.5f*d.gh,
                                   d.gx + 0.5f*d.gw, d.gy + 0.5f*d.gh);
        s->Area[tid] = C717 * (d.gw * d.gh);
    }

    // warp-private cp.async staging (R15-proven structure; rows padded to 136 floats)
    int r1   = lane >> 3;                 // k-rows r1 and r1+4
    int cell = warp*32 + (lane & 7)*4;    // 16B chunk = 4 cells
    bool cvalid = cell < act;
    const char* gA = (const char*)(xin + ((size_t)(b*KDIM + r1)) * NCELL + hw0 + cell);
    const char* gB = (const char*)(xin + ((size_t)(b*KDIM + r1 + 4)) * NCELL + hw0 + cell);
    const size_t stride8 = (size_t)8 * NCELL * 4;
    uint32_t dA = smem_u32(&s->st[0][0][0]) + r1*(STROW*4) + cell*4;
    uint32_t dB = dA + 4*(STROW*4);

    #pragma unroll
    for (int st0 = 0; st0 < 3; st0++) {
        if (cvalid) {
            cp16(dA + st0*STG_B, gA);
            cp16(dB + st0*STG_B, gB);
        }
        cp_commit();
        gA += stride8; gB += stride8;
    }

    __syncthreads();   // Wb / Box / Bv visible

    float acc[2][2][4];
    #pragma unroll
    for (int mt = 0; mt < 2; mt++)
        #pragma unroll
        for (int nt = 0; nt < 2; nt++)
            #pragma unroll
            for (int i = 0; i < 4; i++) acc[mt][nt][i] = 0.0f;

    int C0  = warp*32;
    int g   = lane >> 2, tig = lane & 3;

    #pragma unroll 4
    for (int kb = 0; kb < 32; kb++) {
        cp_wait2();
        __syncwarp();
        const float* stg = &s->st[kb & 3][0][0];

        // B fragments (k8 x n8, col-major spec): b0=(tig, g), b1=(tig+4, g)
        uint32_t b0[2], b1[2];
        #pragma unroll
        for (int nt = 0; nt < 2; nt++) {
            b0[nt] = __float_as_uint(s->Wb[kb*8 + tig    ][nt*8 + g]);
            b1[nt] = __float_as_uint(s->Wb[kb*8 + tig + 4][nt*8 + g]);
        }
        #pragma unroll
        for (int mt = 0; mt < 2; mt++) {
            int m0 = C0 + mt*16 + g;
            uint32_t a0 = tf32_of(stg[ tig     *STROW + m0    ]);
            uint32_t a1 = tf32_of(stg[ tig     *STROW + m0 + 8]);
            uint32_t a2 = tf32_of(stg[(tig + 4)*STROW + m0    ]);
            uint32_t a3 = tf32_of(stg[(tig + 4)*STROW + m0 + 8]);
            mma_tf32(acc[mt][0], a0, a1, a2, a3, b0[0], b1[0]);
            mma_tf32(acc[mt][1], a0, a1, a2, a3, b0[1], b1[1]);
        }

        if (kb + 3 < 32) {
            int st3 = (kb + 3) & 3;
            if (cvalid) {
                cp16(dA + st3*STG_B, gA);
                cp16(dB + st3*STG_B, gB);
            }
            gA += stride8; gB += stride8;
        }
        cp_commit();          // unconditional: keeps wait_group arithmetic valid
    }

    // spill D to smem (stage region reuse), rows stride 18 floats
    __syncthreads();          // every warp done reading all stages
    float* Dsm = &s->st[0][0][0];
    uint32_t dbase = smem_u32(Dsm);
    #pragma unroll
    for (int mt = 0; mt < 2; mt++) {
        #pragma unroll
        for (int nt = 0; nt < 2; nt++) {
            int r0 = C0 + mt*16 + g;
            int cc = nt*8 + tig*2;
            sts64(dbase + (uint32_t)((r0     )*18 + cc)*4, acc[mt][nt][0], acc[mt][nt][1]);
            sts64(dbase + (uint32_t)((r0 + 8 )*18 + cc)*4, acc[mt][nt][2], acc[mt][nt][3]);
        }
    }
    __syncwarp();             // own warp wrote own 32 rows; reads below are own rows

    float lobj = 0.f;
    if (tid < act) {
        float xs[15];
        #pragma unroll
        for (int o = 0; o < 15; o++) xs[o] = Dsm[tid*18 + o] + s->Bv[o];
        int hw = hw0 + tid;
        float fx = (float)(hw % NGRID);
        float fy = (float)(hw / NGRID);
        #pragma unroll
        for (int a = 0; a < 3; a++) {
            float sx = sigm(xs[a*5+0]), sy = sigm(xs[a*5+1]);
            float pw = expf(xs[a*5+2]) * c_aw[a];
            float ph = expf(xs[a*5+3]) * c_ah[a];
            float px = sx + fx, py = sy + fy;
            float pl = px - 0.5f*pw, pr = px + 0.5f*pw;
            float pt = py - 0.5f*ph, pb = py + 0.5f*ph;
            float cpa = C717 * (pw * ph);
            float bad = -1e30f;
            #pragma unroll 2
            for (int j = 0; j < NBOX; j++) {
                float4 gb = s->Box[j];
                float cga = s->Area[j];
                float tlx = fmaxf(pl, gb.x);
                float tly = fmaxf(pt, gb.y);
                float brx = fminf(pr, gb.z);
                float bry = fminf(pb, gb.w);
                float iw = fmaxf(brx - tlx, 0.0f);
                float ih = fmaxf(bry - tly, 0.0f);
                bad = fmaxf(bad, fmaf(iw, ih, -cga));
            }
            if (bad <= cpa) {                     // bestiou <= 0.7
                float conf = sigm(xs[a*5+4]);
                lobj += -safelog(1.0f - conf);
            }
        }
    }

    // single deterministic block reduction (obj only)
    float* red = s->red;
    __syncthreads();
    red[tid] = lobj; __syncthreads();
    for (int st = MAIN_THREADS/2; st > 0; st >>= 1) {
        if (tid < st) red[tid] += red[tid+st];
        __syncthreads();
    }
    if (tid == 0) g_obj[mbid] = red[0];
}

// ---- final reduction, run by the last block to finish ----
__device__ void final_path(SmemFin* s, float* __restrict__ out) {
    int tid = threadIdx.x;
    float oxy = 0.f, owh = 0.f, oobj = 0.f, ocls = 0.f;
    for (int i = tid; i < MAIN_BLOCKS; i += MAIN_THREADS) oobj += g_obj[i];
    for (int i = tid; i < NB*NBOX; i += MAIN_THREADS) {
        float4 c = g_corr[i];
        oxy += c.x; owh += c.y; oobj += c.z; ocls += c.w;
    }
    s->r4[tid] = make_float4(oxy, owh, oobj, ocls);
    __syncthreads();
    for (int st = MAIN_THREADS/2; st > 0; st >>= 1) {
        if (tid < st) {
            float4 a = s->r4[tid], b = s->r4[tid+st];
            s->r4[tid] = make_float4(a.x+b.x, a.y+b.y, a.z+b.z, a.w+b.w);
        }
        __syncthreads();
    }
    if (tid == 0) {
        float4 r = s->r4[0];
        out[0] = r.x + r.y + r.z + r.w;
        out[1] = r.x; out[2] = r.y; out[3] = r.z; out[4] = r.w;
        g_count = 0;
    }
}

// ---- THE kernel: main blocks [0,736), winner blocks [736,1536), fused finale ----
__global__ void __launch_bounds__(MAIN_THREADS)
k_fat(const float* __restrict__ xin, const float* __restrict__ labels,
      const float* __restrict__ Wm, const float* __restrict__ bias,
      float* __restrict__ out) {
    __shared__ SmemU su;
    __shared__ bool is_last;
    int bid = blockIdx.x;
    if (bid < MAIN_BLOCKS) {
        main_path(&su.m, bid, xin, labels, Wm, bias);
    } else {
        cls_path(&su.c, bid - MAIN_BLOCKS, xin, labels, Wm, bias);
    }
    __threadfence();
    __syncthreads();
    if (threadIdx.x == 0) {
        int v = atomicAdd(&g_count, 1);
        is_last = (v == FAT_BLOCKS - 1);
    }
    __syncthreads();
    if (is_last) {
        __threadfence();
        final_path(&su.f, out);
    }
}

extern "C" void kernel_launch(void* const* d_in, const int* in_sizes, int n_in,
                              void* d_out, int out_size) {
    const float* xin    = (const float*)d_in[0];
    const float* labels = (const float*)d_in[1];
    const float* W      = (const float*)d_in[2];
    const float* b      = (const float*)d_in[3];
    float* out = (float*)d_out;

    k_fat<<<FAT_BLOCKS, MAIN_THREADS>>>(xin, labels, W, b, out);
}